// round 10
// baseline (speedup 1.0000x reference)
#include <cuda_runtime.h>
#include <math.h>

// ---------------------------------------------------------------------------
// MultiHeadAttention: out = softmax((qWq^T+bq)(kWk^T+bk)^T / sqrt(64)) (vWv^T+bv) Wo^T + bo
// Shapes: B=4, H=8, S=2048, D=512, hd=64. Mask is a no-op in the reference.
// fp32 everywhere (rel_err target 1e-3; fp32 gives ~1e-6).
// ---------------------------------------------------------------------------

#define NB   4
#define NH   8
#define SEQ  2048
#define DM   512
#define HD   64
#define MROWS (NB * SEQ)   // 8192

// Scratch (allocation-free rule -> __device__ globals). 4 x 16MB = 64MB.
__device__ float g_Q[NB * NH * SEQ * HD];   // [B,H,S,hd]
__device__ float g_K[NB * NH * SEQ * HD];
__device__ float g_V[NB * NH * SEQ * HD];
__device__ float g_A[NB * SEQ * DM];        // attention output, [B,S,D]

// ---------------------------------------------------------------------------
// NT GEMM: C[m,n] = sum_k X[m,k] * W[n,k] + bias[n]
// M=8192, N=512, K=512. Tiles: BM=128, BN=64, BK=16. 256 threads, 8x4 micro.
// MODE 0/1/2: write head-split into g_Q/g_K/g_V. MODE 3: X:=g_A, write [M,N] to ext.
// ---------------------------------------------------------------------------
template <int MODE>
__global__ __launch_bounds__(256)
void proj_kernel(const float* __restrict__ X,
                 const float* __restrict__ W,
                 const float* __restrict__ bias,
                 float* __restrict__ ext_out)
{
    constexpr int BM = 128, BN = 64, BK = 16;
    __shared__ __align__(16) float As[BK][BM + 4];
    __shared__ __align__(16) float Bs[BK][BN + 4];

    const float* Xin = (MODE == 3) ? g_A : X;

    const int tid = threadIdx.x;        // 0..255
    const int tx  = tid & 15;           // 0..15 -> 4 cols each (BN=64)
    const int ty  = tid >> 4;           // 0..15 -> 8 rows each (BM=128)
    const int m0  = blockIdx.y * BM;
    const int n0  = blockIdx.x * BN;

    const int lr = tid >> 2;            // 0..63
    const int lc = (tid & 3) * 4;       // 0,4,8,12

    const float* Aptr0 = Xin + (size_t)(m0 + lr) * DM + lc;
    const float* Aptr1 = Aptr0 + (size_t)64 * DM;
    const float* Bptr  = W   + (size_t)(n0 + lr) * DM + lc;

    float acc[8][4];
#pragma unroll
    for (int i = 0; i < 8; i++)
#pragma unroll
        for (int j = 0; j < 4; j++) acc[i][j] = 0.f;

    for (int k0 = 0; k0 < DM; k0 += BK) {
        float4 a0 = *(const float4*)(Aptr0 + k0);
        float4 a1 = *(const float4*)(Aptr1 + k0);
        float4 b0 = *(const float4*)(Bptr  + k0);
        __syncthreads();
        As[lc + 0][lr]      = a0.x; As[lc + 1][lr]      = a0.y;
        As[lc + 2][lr]      = a0.z; As[lc + 3][lr]      = a0.w;
        As[lc + 0][lr + 64] = a1.x; As[lc + 1][lr + 64] = a1.y;
        As[lc + 2][lr + 64] = a1.z; As[lc + 3][lr + 64] = a1.w;
        Bs[lc + 0][lr]      = b0.x; Bs[lc + 1][lr]      = b0.y;
        Bs[lc + 2][lr]      = b0.z; Bs[lc + 3][lr]      = b0.w;
        __syncthreads();
#pragma unroll
        for (int kk = 0; kk < BK; kk++) {
            float4 av0 = *(const float4*)&As[kk][ty * 8];
            float4 av1 = *(const float4*)&As[kk][ty * 8 + 4];
            float4 bv  = *(const float4*)&Bs[kk][tx * 4];
            float a[8] = {av0.x, av0.y, av0.z, av0.w, av1.x, av1.y, av1.z, av1.w};
            float b[4] = {bv.x, bv.y, bv.z, bv.w};
#pragma unroll
            for (int i = 0; i < 8; i++)
#pragma unroll
                for (int j = 0; j < 4; j++)
                    acc[i][j] = fmaf(a[i], b[j], acc[i][j]);
        }
    }

    const int col = n0 + tx * 4;
    float4 bvv = *(const float4*)&bias[col];
    float bb[4] = {bvv.x, bvv.y, bvv.z, bvv.w};

    float* outp;
    if (MODE == 0) outp = g_Q;
    else if (MODE == 1) outp = g_K;
    else if (MODE == 2) outp = g_V;
    else outp = ext_out;

#pragma unroll
    for (int i = 0; i < 8; i++) {
        const int m = m0 + ty * 8 + i;
        float4 v;
        v.x = acc[i][0] + bb[0];
        v.y = acc[i][1] + bb[1];
        v.z = acc[i][2] + bb[2];
        v.w = acc[i][3] + bb[3];
        if (MODE < 3) {
            const int b = m >> 11;          // / SEQ
            const int s = m & (SEQ - 1);
            const int h = col >> 6;         // / HD
            const int d = col & (HD - 1);
            *(float4*)&outp[(((size_t)(b * NH + h) * SEQ) + s) * HD + d] = v;
        } else {
            *(float4*)&outp[(size_t)m * DM + col] = v;
        }
    }
}

// ---------------------------------------------------------------------------
// Flash attention: per (b,h) x 128-query block, stream 64-key tiles.
// Q pre-scaled by 1/8 at load. Online softmax; P staged transposed for PV.
// Output written into g_A as [B,S,D] (heads re-interleaved).
// ---------------------------------------------------------------------------
__global__ __launch_bounds__(256, 2)
void flash_kernel()
{
    constexpr int BM = 128, BN = 64;
    constexpr int QS = BM + 4;   // 132
    constexpr int KS = BN + 4;   // 68
    constexpr int VS = HD + 4;   // 68
    constexpr int PS = BM + 4;   // 132

    extern __shared__ __align__(16) float sm[];
    float* Qs = sm;                     // [HD][QS]  transposed: Qs[d][r]
    float* Ks = Qs + HD * QS;           // [HD][KS]  transposed: Ks[d][t]
    float* Vs = Ks + HD * KS;           // [BN][VS]  natural:    Vs[t][d]
    float* Ps = Vs + BN * VS;           // [BN][PS]  transposed: Ps[t][r]

    const int tid = threadIdx.x;
    const int tx  = tid & 15;           // cols (keys / dims), 4 each
    const int ty  = tid >> 4;           // rows (queries), 8 each
    const int s0  = blockIdx.x * BM;
    const int bh  = blockIdx.y;         // b*NH + h

    const float* Qg = g_Q + (size_t)bh * SEQ * HD;
    const float* Kg = g_K + (size_t)bh * SEQ * HD;
    const float* Vg = g_V + (size_t)bh * SEQ * HD;

    const int lr0 = tid >> 4;           // 0..15
    const int lc  = (tid & 15) * 4;     // 0..60

    // Load Q tile (scaled by 1/sqrt(hd)=0.125), transposed.
#pragma unroll
    for (int it = 0; it < 8; it++) {
        const int r = lr0 + it * 16;    // 0..127
        float4 q = *(const float4*)&Qg[(size_t)(s0 + r) * HD + lc];
        Qs[(lc + 0) * QS + r] = q.x * 0.125f;
        Qs[(lc + 1) * QS + r] = q.y * 0.125f;
        Qs[(lc + 2) * QS + r] = q.z * 0.125f;
        Qs[(lc + 3) * QS + r] = q.w * 0.125f;
    }

    float o[8][4];
    float mrow[8], lrow[8];
#pragma unroll
    for (int i = 0; i < 8; i++) {
        mrow[i] = -1e30f;
        lrow[i] = 0.f;
#pragma unroll
        for (int j = 0; j < 4; j++) o[i][j] = 0.f;
    }

    for (int kt = 0; kt < SEQ / BN; kt++) {
        const int t0 = kt * BN;
        __syncthreads();   // prior PV reads of Ks/Vs/Ps done
#pragma unroll
        for (int it = 0; it < 4; it++) {
            const int r = lr0 + it * 16;   // 0..63
            float4 kv = *(const float4*)&Kg[(size_t)(t0 + r) * HD + lc];
            Ks[(lc + 0) * KS + r] = kv.x;
            Ks[(lc + 1) * KS + r] = kv.y;
            Ks[(lc + 2) * KS + r] = kv.z;
            Ks[(lc + 3) * KS + r] = kv.w;
            float4 vv = *(const float4*)&Vg[(size_t)(t0 + r) * HD + lc];
            *(float4*)&Vs[r * VS + lc] = vv;
        }
        __syncthreads();

        // S = (Q*0.125) K^T  : 128x64, K-dim = 64
        float s[8][4];
#pragma unroll
        for (int i = 0; i < 8; i++)
#pragma unroll
            for (int j = 0; j < 4; j++) s[i][j] = 0.f;

#pragma unroll 8
        for (int d = 0; d < HD; d++) {
            float4 av0 = *(const float4*)&Qs[d * QS + ty * 8];
            float4 av1 = *(const float4*)&Qs[d * QS + ty * 8 + 4];
            float4 bv  = *(const float4*)&Ks[d * KS + tx * 4];
            float a[8] = {av0.x, av0.y, av0.z, av0.w, av1.x, av1.y, av1.z, av1.w};
            float b[4] = {bv.x, bv.y, bv.z, bv.w};
#pragma unroll
            for (int i = 0; i < 8; i++)
#pragma unroll
                for (int j = 0; j < 4; j++)
                    s[i][j] = fmaf(a[i], b[j], s[i][j]);
        }

        // Online softmax (row reductions across the 16-thread tx group).
#pragma unroll
        for (int i = 0; i < 8; i++) {
            float mx = s[i][0];
#pragma unroll
            for (int j = 1; j < 4; j++) mx = fmaxf(mx, s[i][j]);
#pragma unroll
            for (int off = 8; off > 0; off >>= 1)
                mx = fmaxf(mx, __shfl_xor_sync(0xffffffffu, mx, off, 16));
            const float mnew = fmaxf(mrow[i], mx);
            const float corr = __expf(mrow[i] - mnew);
            float ps = 0.f;
#pragma unroll
            for (int j = 0; j < 4; j++) {
                const float p = __expf(s[i][j] - mnew);
                ps += p;
                s[i][j] = p;
            }
#pragma unroll
            for (int off = 8; off > 0; off >>= 1)
                ps += __shfl_xor_sync(0xffffffffu, ps, off, 16);
            lrow[i] = lrow[i] * corr + ps;
            mrow[i] = mnew;
#pragma unroll
            for (int j = 0; j < 4; j++) o[i][j] *= corr;
        }

        // Stage P transposed: Ps[t][r]
#pragma unroll
        for (int i = 0; i < 8; i++)
#pragma unroll
            for (int j = 0; j < 4; j++)
                Ps[(tx * 4 + j) * PS + ty * 8 + i] = s[i][j];
        __syncthreads();

        // O += P V : 128x64, K-dim = 64 keys
#pragma unroll 8
        for (int t = 0; t < BN; t++) {
            float4 pv0 = *(const float4*)&Ps[t * PS + ty * 8];
            float4 pv1 = *(const float4*)&Ps[t * PS + ty * 8 + 4];
            float4 vv  = *(const float4*)&Vs[t * VS + tx * 4];
            float p[8] = {pv0.x, pv0.y, pv0.z, pv0.w, pv1.x, pv1.y, pv1.z, pv1.w};
            float vb[4] = {vv.x, vv.y, vv.z, vv.w};
#pragma unroll
            for (int i = 0; i < 8; i++)
#pragma unroll
                for (int j = 0; j < 4; j++)
                    o[i][j] = fmaf(p[i], vb[j], o[i][j]);
        }
    }

    // Epilogue: normalize and write to [B,S,D] layout.
    const int b = bh >> 3;
    const int h = bh & (NH - 1);
#pragma unroll
    for (int i = 0; i < 8; i++) {
        const float inv = 1.0f / lrow[i];
        const int srow = s0 + ty * 8 + i;
        float4 v;
        v.x = o[i][0] * inv;
        v.y = o[i][1] * inv;
        v.z = o[i][2] * inv;
        v.w = o[i][3] * inv;
        *(float4*)&g_A[((size_t)(b * SEQ) + srow) * DM + h * HD + tx * 4] = v;
    }
}

// ---------------------------------------------------------------------------
// kernel_launch: 5 launches, default stream, graph-capturable.
// Input order: q,k,v,mask,Wq,bq,Wk,bk,Wv,bv,Wo,bo
// ---------------------------------------------------------------------------
extern "C" void kernel_launch(void* const* d_in, const int* in_sizes, int n_in,
                              void* d_out, int out_size)
{
    (void)in_sizes; (void)n_in; (void)out_size;
    const float* q  = (const float*)d_in[0];
    const float* k  = (const float*)d_in[1];
    const float* v  = (const float*)d_in[2];
    // d_in[3] = mask (int32) — a no-op in the reference math
    const float* Wq = (const float*)d_in[4];
    const float* bq = (const float*)d_in[5];
    const float* Wk = (const float*)d_in[6];
    const float* bk = (const float*)d_in[7];
    const float* Wv = (const float*)d_in[8];
    const float* bv = (const float*)d_in[9];
    const float* Wo = (const float*)d_in[10];
    const float* bo = (const float*)d_in[11];
    float* out = (float*)d_out;

    const dim3 pgrid(DM / 64, MROWS / 128);   // (8, 64)

    proj_kernel<0><<<pgrid, 256>>>(q, Wq, bq, nullptr);
    proj_kernel<1><<<pgrid, 256>>>(k, Wk, bk, nullptr);
    proj_kernel<2><<<pgrid, 256>>>(v, Wv, bv, nullptr);

    const int smem_bytes = (HD * (128 + 4) + HD * (64 + 4) +
                            64 * (HD + 4) + 64 * (128 + 4)) * (int)sizeof(float); // 102400
    cudaFuncSetAttribute(flash_kernel,
                         cudaFuncAttributeMaxDynamicSharedMemorySize, smem_bytes);
    flash_kernel<<<dim3(SEQ / 128, NB * NH), 256, smem_bytes>>>();

    proj_kernel<3><<<pgrid, 256>>>(nullptr, Wo, bo, out);
}